// round 8
// baseline (speedup 1.0000x reference)
#include <cuda_runtime.h>
#include <math.h>
#include <stdint.h>

// ---------------- problem constants ----------------
#define B_ 2
#define E_ 256
#define NH_ 8
#define NL_ 4
#define NP_ 4
#define DF_ 1024
#define NLAYERS_ 6
#define HD_ 32
#define S_ 10548
#define M_ (B_*S_)          // 21096 query rows

__device__ __constant__ int c_LD[4] = {4, 2, 1, 1};
__device__ __constant__ int c_LH[4] = {48, 24, 12, 6};
__device__ __constant__ int c_LW[4] = {48, 24, 12, 6};

// ---------------- scratch (allocation-free) ----------------
__device__ float g_x  [M_*E_];
__device__ float g_xr [M_*E_];
__device__ float g_pos[M_*E_];
__device__ float g_q  [M_*E_];
__device__ float g_val[M_*E_];
__device__ float g_sam[M_*E_];
__device__ float g_tmp[M_*E_];
__device__ float g_oa [M_*512];    // packed: [0,384) offsets, [384,512) attn logits
__device__ float g_hid[M_*DF_];

// fragment-packed tf32 weights: per layer (K/8)*(N/8)*32 float2
__device__ float2 g_WvalF[NLAYERS_*E_*E_/2];
__device__ float2 g_WqaF [NLAYERS_*E_*512/2];
__device__ float2 g_WoutF[NLAYERS_*E_*E_/2];
__device__ float2 g_Wff1F[NLAYERS_*E_*DF_/2];
__device__ float2 g_Wff2F[NLAYERS_*DF_*E_/2];
__device__ float  g_bqa  [NLAYERS_*512];

// ---------------- tf32 helpers ----------------
__device__ __forceinline__ unsigned tf32_bits(float x)
{
    unsigned r;
    asm("cvt.rna.tf32.f32 %0, %1;\n" : "=r"(r) : "f"(x));
    return r;
}
__device__ __forceinline__ float tf32_round(float x)
{
    return __uint_as_float(tf32_bits(x));
}

__device__ __forceinline__ void mma_tf32(float c[4], const unsigned a[4], const unsigned b[2])
{
    asm volatile("mma.sync.aligned.m16n8k8.row.col.f32.tf32.tf32.f32 "
        "{%0,%1,%2,%3}, {%4,%5,%6,%7}, {%8,%9}, {%0,%1,%2,%3};\n"
        : "+f"(c[0]), "+f"(c[1]), "+f"(c[2]), "+f"(c[3])
        : "r"(a[0]), "r"(a[1]), "r"(a[2]), "r"(a[3]), "r"(b[0]), "r"(b[1]));
}

__device__ __forceinline__ void cp_async16(void* smem, const void* gmem, bool valid)
{
    unsigned saddr = (unsigned)__cvta_generic_to_shared(smem);
    int sz = valid ? 16 : 0;
    asm volatile("cp.async.cg.shared.global [%0], [%1], 16, %2;\n"
                 :: "r"(saddr), "l"(gmem), "r"(sz));
}
__device__ __forceinline__ void cp_commit() { asm volatile("cp.async.commit_group;\n"); }
template<int N> __device__ __forceinline__ void cp_wait() { asm volatile("cp.async.wait_group %0;\n" :: "n"(N)); }

#define LDSM_X4(r0,r1,r2,r3,addr) \
    asm volatile("ldmatrix.sync.aligned.m8n8.x4.shared.b16 {%0,%1,%2,%3}, [%4];\n" \
        : "=r"(r0), "=r"(r1), "=r"(r2), "=r"(r3) : "r"(addr))

// ---------------- weight fragment packing ----------------
// src[K,N] (row-major) -> dst fragments: dst[((ks*NtotTiles + tileOff + ntile)*32 + lane)]
//   = float2{ tf32(src[ks*8+r][ntile*8+q]), tf32(src[ks*8+r+4][ntile*8+q]) }
// with q = lane>>2, r = lane&3  (PTX m16n8k8 B-fragment mapping)
__global__ void pack_frag(const float* __restrict__ src, float2* __restrict__ dst,
                          int K, int Nsrc, int NtotTiles, int tileOff)
{
    int idx = blockIdx.x * blockDim.x + threadIdx.x;
    int l = blockIdx.z;
    int tot = (K/8) * (Nsrc/8) * 32;
    if (idx >= tot) return;
    int lane = idx & 31;
    int t = idx >> 5;
    int ntile = t % (Nsrc/8);
    int ks    = t / (Nsrc/8);
    int q = lane >> 2, r = lane & 3;
    const float* s = src + (size_t)l * K * Nsrc;
    float v0 = s[(size_t)(ks*8 + r    ) * Nsrc + ntile*8 + q];
    float v1 = s[(size_t)(ks*8 + r + 4) * Nsrc + ntile*8 + q];
    float2* d = dst + (size_t)l * (K/8) * NtotTiles * 32;
    d[((size_t)ks * NtotTiles + tileOff + ntile) * 32 + lane] =
        make_float2(tf32_round(v0), tf32_round(v1));
}

__global__ void pack_bias_qa(const float* __restrict__ boff, const float* __restrict__ battn)
{
    int idx = blockIdx.x * blockDim.x + threadIdx.x;
    if (idx < NLAYERS_ * 512) {
        int l = idx >> 9, c = idx & 511;
        g_bqa[idx] = (c < 384) ? boff[l*384 + c] : battn[l*128 + (c - 384)];
    }
}

// ---------------- coalesced transposing init (per level) ----------------
__global__ void init_t_kernel(const float* __restrict__ f, const float* __restrict__ p,
                              const float* __restrict__ le_row, int n, int s0)
{
    __shared__ float tf[32][33];
    __shared__ float tp[32][33];
    int i0 = blockIdx.x * 32;
    int e0 = blockIdx.y * 32;
    int b  = blockIdx.z;
    int tx = threadIdx.x, ty = threadIdx.y;

    int ig = i0 + tx;
    int eg = e0 + ty;
    if (ig < n) {
        size_t src = (size_t)(b*E_ + eg) * n + ig;
        tf[ty][tx] = f[src];
        tp[ty][tx] = p[src];
    }
    __syncthreads();

    int iw = i0 + ty;
    int ew = e0 + tx;
    if (iw < n) {
        size_t dst = (size_t)(b*S_ + s0 + iw) * E_ + ew;
        float xv = tf[tx][ty];
        float pv = tp[tx][ty] + le_row[ew];
        g_x[dst]   = xv;
        g_xr[dst]  = tf32_round(xv);
        g_pos[dst] = pv;
        g_q[dst]   = tf32_round(xv + pv);
    }
}

// ---------------- tf32 mma GEMM: A via cp.async+ldmatrix, B via packed frags --
// C[M,N] = A @ W + bias. 256 threads, warps 2 rows x 4 cols.
template<int BMt, int BNt>
__global__ void __launch_bounds__(256, (BMt==64 ? 4 : 2))
fg_gemm(const float* __restrict__ A, const float2* __restrict__ Wf,
        const float* __restrict__ bias, float* __restrict__ C,
        int M, int N, int K, int mode)
{
    constexpr int MI   = BMt/32;       // m16 tiles per warp (warp m = BMt/2)
    constexpr int NI   = BNt/32;       // n8 tiles per warp (warp n = BNt/4)
    constexpr int ACH  = BMt/32;       // A 16B chunks per thread
    constexpr int ASTR = 36;
    constexpr int A_FL = BMt*ASTR;

    extern __shared__ float smp[];

    int tid  = threadIdx.x;
    int lane = tid & 31;
    int wid  = tid >> 5;
    int bm = blockIdx.y * BMt;
    int bn = blockIdx.x * BNt;
    int wm = (wid >> 2) * (BMt/2);
    int wn = (wid & 3) * (BNt/4);
    int q = lane >> 2;
    int r = lane & 3;
    (void)q; (void)r;

    float acc[MI][NI][4];
    #pragma unroll
    for (int mi = 0; mi < MI; mi++)
        #pragma unroll
        for (int ni = 0; ni < NI; ni++)
            #pragma unroll
            for (int j = 0; j < 4; j++) acc[mi][ni][j] = 0.f;

    int arow[ACH], ac[ACH]; bool aval[ACH];
    #pragma unroll
    for (int i = 0; i < ACH; i++) {
        int idx = tid + i*256; arow[i] = idx >> 3; ac[i] = idx & 7;
        aval[i] = (bm + arow[i]) < M;
    }

    int nkt = K / 32;
    int ntiles = N >> 3;
    int btile0 = (bn >> 3) + (wn >> 3);

    int mt = lane >> 3;
    int rbase = (mt & 1)*8 + (lane & 7);
    int koff = (mt >> 1)*4;
    unsigned smem_u32 = (unsigned)__cvta_generic_to_shared(smp);

    // prologue: stages 0 and 1 (A only)
    {
        #pragma unroll
        for (int i = 0; i < ACH; i++)
            cp_async16(smp + arow[i]*ASTR + ac[i]*4,
                       A + (size_t)(aval[i] ? (bm + arow[i]) : 0) * K + ac[i]*4, aval[i]);
        cp_commit();
        if (nkt > 1) {
            #pragma unroll
            for (int i = 0; i < ACH; i++)
                cp_async16(smp + A_FL + arow[i]*ASTR + ac[i]*4,
                           A + (size_t)(aval[i] ? (bm + arow[i]) : 0) * K + 32 + ac[i]*4, aval[i]);
        }
        cp_commit();
    }

    for (int kt = 0; kt < nkt; kt++) {
        int st = kt % 3;
        if (kt + 2 < nkt) {
            float* As = smp + ((kt + 2) % 3) * A_FL;
            int kg = (kt + 2) * 32;
            #pragma unroll
            for (int i = 0; i < ACH; i++)
                cp_async16(As + arow[i]*ASTR + ac[i]*4,
                           A + (size_t)(aval[i] ? (bm + arow[i]) : 0) * K + kg + ac[i]*4, aval[i]);
        }
        cp_commit();
        cp_wait<2>();
        __syncthreads();

        unsigned abase = smem_u32 + (unsigned)(st*A_FL)*4u
                       + (unsigned)((wm + rbase)*ASTR + koff)*4u;
        const float2* bbase = Wf + ((size_t)(kt*4) * ntiles + btile0) * 32 + lane;

        #pragma unroll
        for (int ks = 0; ks < 4; ks++) {
            unsigned af[MI][4], bf[NI][2];
            #pragma unroll
            for (int mi = 0; mi < MI; mi++) {
                LDSM_X4(af[mi][0], af[mi][1], af[mi][2], af[mi][3],
                        abase + (unsigned)((mi*16*ASTR + ks*8)*4));
            }
            #pragma unroll
            for (int ni = 0; ni < NI; ni++) {
                float2 bv = bbase[((size_t)ks * ntiles + ni) * 32];
                bf[ni][0] = __float_as_uint(bv.x);
                bf[ni][1] = __float_as_uint(bv.y);
            }
            #pragma unroll
            for (int mi = 0; mi < MI; mi++)
                #pragma unroll
                for (int ni = 0; ni < NI; ni++)
                    mma_tf32(acc[mi][ni], af[mi], bf[ni]);
        }
        __syncthreads();
    }

    // epilogue
    int qq = lane >> 2, rr = lane & 3;
    #pragma unroll
    for (int mi = 0; mi < MI; mi++) {
        #pragma unroll
        for (int ni = 0; ni < NI; ni++) {
            int row = bm + wm + mi*16 + qq;
            int col = bn + wn + ni*8 + rr*2;
            float bx = bias[col], by = bias[col+1];
            if (row < M) {
                float v0 = acc[mi][ni][0] + bx;
                float v1 = acc[mi][ni][1] + by;
                if (mode == 1) { v0 = tf32_round(fmaxf(v0, 0.f)); v1 = tf32_round(fmaxf(v1, 0.f)); }
                *(float2*)&C[(size_t)row * N + col] = make_float2(v0, v1);
            }
            if (row + 8 < M) {
                float v2 = acc[mi][ni][2] + bx;
                float v3 = acc[mi][ni][3] + by;
                if (mode == 1) { v2 = tf32_round(fmaxf(v2, 0.f)); v3 = tf32_round(fmaxf(v3, 0.f)); }
                *(float2*)&C[(size_t)(row + 8) * N + col] = make_float2(v2, v3);
            }
        }
    }
}

// ---------------- deformable sampling, float4-vectorized ----------------
__global__ void sample_kernel()
{
    int warpIdx = (blockIdx.x * blockDim.x + threadIdx.x) >> 5;
    int lane  = threadIdx.x & 31;
    if (warpIdx >= M_ * NH_) return;
    int h  = warpIdx / M_;
    int bs = warpIdx - h * M_;
    int b  = bs / S_;
    int s  = bs % S_;
    int eg = lane & 7;
    int pg = lane >> 3;

    int lvl_q, iq;
    if (s < 9216)       { lvl_q = 0; iq = s;         }
    else if (s < 10368) { lvl_q = 1; iq = s - 9216;  }
    else if (s < 10512) { lvl_q = 2; iq = s - 10368; }
    else                { lvl_q = 3; iq = s - 10512; }
    int Wq = c_LW[lvl_q], Hq = c_LH[lvl_q], Dq = c_LD[lvl_q];
    int xq = iq % Wq;
    int t  = iq / Wq;
    int yq = t % Hq;
    int zq = t / Hq;
    float rx = (xq + 0.5f) / (float)Wq;
    float ry = (yq + 0.5f) / (float)Hq;
    float rz = (zq + 0.5f) / (float)Dq;

    const float4* lg4 = (const float4*)(g_oa + (size_t)bs * 512 + 384 + h * 16);
    float lv[16];
    {
        float4 v0 = lg4[0], v1 = lg4[1], v2 = lg4[2], v3 = lg4[3];
        lv[0]=v0.x; lv[1]=v0.y; lv[2]=v0.z; lv[3]=v0.w;
        lv[4]=v1.x; lv[5]=v1.y; lv[6]=v1.z; lv[7]=v1.w;
        lv[8]=v2.x; lv[9]=v2.y; lv[10]=v2.z; lv[11]=v2.w;
        lv[12]=v3.x; lv[13]=v3.y; lv[14]=v3.z; lv[15]=v3.w;
    }
    float mx = -1e30f;
    #pragma unroll
    for (int j = 0; j < 16; j++) mx = fmaxf(mx, lv[j]);
    float ssum = 0.f;
    #pragma unroll
    for (int j = 0; j < 16; j++) { lv[j] = __expf(lv[j] - mx); ssum += lv[j]; }
    float inv = 1.f / ssum;

    const float* offp = g_oa + (size_t)bs * 512 + h * (NL_*NP_*3);

    const int LDc[4]  = {4, 2, 1, 1};
    const int LHc[4]  = {48, 24, 12, 6};
    const int LWc[4]  = {48, 24, 12, 6};
    const int LS0c[4] = {0, 9216, 10368, 10512};

    float4 acc = make_float4(0.f, 0.f, 0.f, 0.f);

    #pragma unroll
    for (int lvl = 0; lvl < 4; lvl++) {
        const int Dl = LDc[lvl], Hl = LHc[lvl], Wl = LWc[lvl];
        const float* vb = g_val + ((size_t)b * S_ + LS0c[lvl]) * E_ + h * HD_ + eg * 4;

        float aw = lv[lvl*4 + pg] * inv;
        float ox = offp[lvl*12 + pg*3 + 0];
        float oy = offp[lvl*12 + pg*3 + 1];
        float oz = offp[lvl*12 + pg*3 + 2];
        float cx = rx * (float)Wl + ox - 0.5f;
        float cy = ry * (float)Hl + oy - 0.5f;
        float cz = rz * (float)Dl + oz - 0.5f;
        float xf = floorf(cx), yf = floorf(cy), zf = floorf(cz);
        float fx = cx - xf, fy = cy - yf, fz = cz - zf;
        int x0 = (int)xf, y0 = (int)yf, z0 = (int)zf;

        #pragma unroll
        for (int dz = 0; dz < 2; dz++) {
            int iz = z0 + dz;
            float wz = dz ? fz : 1.f - fz;
            bool vz = (iz >= 0) & (iz < Dl);
            int cz_i = min(max(iz, 0), Dl - 1);
            #pragma unroll
            for (int dy = 0; dy < 2; dy++) {
                int iy = y0 + dy;
                float wy = dy ? fy : 1.f - fy;
                bool vy = (iy >= 0) & (iy < Hl);
                int cy_i = min(max(iy, 0), Hl - 1);
                #pragma unroll
                for (int dx = 0; dx < 2; dx++) {
                    int ix = x0 + dx;
                    float wx = dx ? fx : 1.f - fx;
                    bool vx = (ix >= 0) & (ix < Wl);
                    int cx_i = min(max(ix, 0), Wl - 1);
                    float wgt = (vz & vy & vx) ? (aw * wx * wy * wz) : 0.f;
                    int idx = (cz_i*Hl + cy_i)*Wl + cx_i;
                    float4 v = *(const float4*)(vb + (size_t)idx * E_);
                    acc.x += wgt * v.x;
                    acc.y += wgt * v.y;
                    acc.z += wgt * v.z;
                    acc.w += wgt * v.w;
                }
            }
        }
    }

    #pragma unroll
    for (int o = 8; o <= 16; o <<= 1) {
        acc.x += __shfl_xor_sync(0xFFFFFFFFu, acc.x, o);
        acc.y += __shfl_xor_sync(0xFFFFFFFFu, acc.y, o);
        acc.z += __shfl_xor_sync(0xFFFFFFFFu, acc.z, o);
        acc.w += __shfl_xor_sync(0xFFFFFFFFu, acc.w, o);
    }

    if (lane < 8) {
        float4 o4;
        o4.x = tf32_round(acc.x);
        o4.y = tf32_round(acc.y);
        o4.z = tf32_round(acc.z);
        o4.w = tf32_round(acc.w);
        *(float4*)(g_sam + (size_t)bs * E_ + h * HD_ + lane * 4) = o4;
    }
}

// ---------------- fused residual + LayerNorm (+ rounded copies) -------------
__device__ __forceinline__ float warp_sum(float v)
{
    #pragma unroll
    for (int o = 16; o > 0; o >>= 1) v += __shfl_xor_sync(0xFFFFFFFFu, v, o);
    return v;
}

__global__ void ln_kernel(const float* __restrict__ x, const float* __restrict__ r,
                          const float* __restrict__ g, const float* __restrict__ be,
                          float* __restrict__ out, float* __restrict__ outr,
                          const float* __restrict__ pos, float* __restrict__ qout)
{
    int row = blockIdx.x;
    int e = threadIdx.x;
    size_t base = (size_t)row * E_;
    float v = x[base + e] + r[base + e];
    __shared__ float sh[8];
    float ws = warp_sum(v);
    int w = e >> 5, ln = e & 31;
    if (ln == 0) sh[w] = ws;
    __syncthreads();
    float mean = 0.f;
    #pragma unroll
    for (int i = 0; i < 8; i++) mean += sh[i];
    mean *= (1.f / E_);
    __syncthreads();
    float d = v - mean;
    float ws2 = warp_sum(d * d);
    if (ln == 0) sh[w] = ws2;
    __syncthreads();
    float var = 0.f;
    #pragma unroll
    for (int i = 0; i < 8; i++) var += sh[i];
    var *= (1.f / E_);
    float y = d * rsqrtf(var + 1e-5f) * g[e] + be[e];
    out[base + e] = y;
    if (outr) outr[base + e] = tf32_round(y);
    if (qout) qout[base + e] = tf32_round(y + pos[base + e]);
}

// ---------------- host launcher ----------------
#define SMEM128 (3*128*36*4)   // 55296
#define SMEM64  (3*64*36*4)    // 27648

extern "C" void kernel_launch(void* const* d_in, const int* in_sizes, int n_in,
                              void* d_out, int out_size)
{
    (void)in_sizes; (void)n_in; (void)out_size;
    const float* f0 = (const float*)d_in[0];
    const float* p0 = (const float*)d_in[1];
    const float* f1 = (const float*)d_in[2];
    const float* p1 = (const float*)d_in[3];
    const float* f2 = (const float*)d_in[4];
    const float* p2 = (const float*)d_in[5];
    const float* f3 = (const float*)d_in[6];
    const float* p3 = (const float*)d_in[7];
    const float* le = (const float*)d_in[8];
    const float* W_off  = (const float*)d_in[9];
    const float* b_off  = (const float*)d_in[10];
    const float* W_attn = (const float*)d_in[11];
    const float* b_attn = (const float*)d_in[12];
    const float* W_val  = (const float*)d_in[13];
    const float* b_val  = (const float*)d_in[14];
    const float* W_out  = (const float*)d_in[15];
    const float* b_out  = (const float*)d_in[16];
    const float* ln1_g  = (const float*)d_in[17];
    const float* ln1_b  = (const float*)d_in[18];
    const float* W_ff1  = (const float*)d_in[19];
    const float* b_ff1  = (const float*)d_in[20];
    const float* W_ff2  = (const float*)d_in[21];
    const float* b_ff2  = (const float*)d_in[22];
    const float* ln2_g  = (const float*)d_in[23];
    const float* ln2_b  = (const float*)d_in[24];

    float *px, *pxr, *ppos, *pq, *pval, *psam, *ptmp, *phid, *poa, *pbqa;
    float2 *pWvalF, *pWqaF, *pWoutF, *pWff1F, *pWff2F;
    cudaGetSymbolAddress((void**)&px,     g_x);
    cudaGetSymbolAddress((void**)&pxr,    g_xr);
    cudaGetSymbolAddress((void**)&ppos,   g_pos);
    cudaGetSymbolAddress((void**)&pq,     g_q);
    cudaGetSymbolAddress((void**)&pval,   g_val);
    cudaGetSymbolAddress((void**)&psam,   g_sam);
    cudaGetSymbolAddress((void**)&ptmp,   g_tmp);
    cudaGetSymbolAddress((void**)&phid,   g_hid);
    cudaGetSymbolAddress((void**)&poa,    g_oa);
    cudaGetSymbolAddress((void**)&pWvalF, g_WvalF);
    cudaGetSymbolAddress((void**)&pWqaF,  g_WqaF);
    cudaGetSymbolAddress((void**)&pWoutF, g_WoutF);
    cudaGetSymbolAddress((void**)&pWff1F, g_Wff1F);
    cudaGetSymbolAddress((void**)&pWff2F, g_Wff2F);
    cudaGetSymbolAddress((void**)&pbqa,   g_bqa);

    cudaFuncSetAttribute(fg_gemm<128,128>, cudaFuncAttributeMaxDynamicSharedMemorySize, SMEM128);
    cudaFuncSetAttribute(fg_gemm<64,64>,   cudaFuncAttributeMaxDynamicSharedMemorySize, SMEM64);

    // weight fragment packing
    {
        // pack_frag(src, dst, K, Nsrc, NtotTiles, tileOff); grid.z = layers
        int n;
        n = (256/8)*(256/8)*32;
        pack_frag<<<dim3((n+255)/256, 1, NLAYERS_), 256>>>(W_val, pWvalF, 256, 256, 32, 0);
        pack_frag<<<dim3((n+255)/256, 1, NLAYERS_), 256>>>(W_out, pWoutF, 256, 256, 32, 0);
        n = (256/8)*(1024/8)*32;
        pack_frag<<<dim3((n+255)/256, 1, NLAYERS_), 256>>>(W_ff1, pWff1F, 256, 1024, 128, 0);
        n = (1024/8)*(256/8)*32;
        pack_frag<<<dim3((n+255)/256, 1, NLAYERS_), 256>>>(W_ff2, pWff2F, 1024, 256, 32, 0);
        n = (256/8)*(384/8)*32;
        pack_frag<<<dim3((n+255)/256, 1, NLAYERS_), 256>>>(W_off, pWqaF, 256, 384, 64, 0);
        n = (256/8)*(128/8)*32;
        pack_frag<<<dim3((n+255)/256, 1, NLAYERS_), 256>>>(W_attn, pWqaF, 256, 128, 64, 48);
        pack_bias_qa<<<(NLAYERS_*512 + 255)/256, 256>>>(b_off, b_attn);
    }

    // transposing init, one launch per level
    {
        dim3 blk(32, 32);
        init_t_kernel<<<dim3(288, 8, B_), blk>>>(f0, p0, le + 0*E_, 9216, 0);
        init_t_kernel<<<dim3( 36, 8, B_), blk>>>(f1, p1, le + 1*E_, 1152, 9216);
        init_t_kernel<<<dim3(  5, 8, B_), blk>>>(f2, p2, le + 2*E_,  144, 10368);
        init_t_kernel<<<dim3(  2, 8, B_), blk>>>(f3, p3, le + 3*E_,   36, 10512);
    }

    const int GM64  = (M_ + 63) / 64;    // 330
    const int GM128 = (M_ + 127) / 128;  // 165
    // per-layer fragment strides (float2 units): K*N/2
    const size_t sVal = (size_t)256*256/2;
    const size_t sQa  = (size_t)256*512/2;
    const size_t sFf1 = (size_t)256*1024/2;
    const size_t sFf2 = (size_t)1024*256/2;

    for (int l = 0; l < NLAYERS_; l++) {
        fg_gemm<64,64><<<dim3(E_/64, GM64), 256, SMEM64>>>(pxr, pWvalF + l*sVal,
                                           b_val + l*E_, pval, M_, E_, E_, 0);
        fg_gemm<128,128><<<dim3(512/128, GM128), 256, SMEM128>>>(pq, pWqaF + l*sQa,
                                            pbqa + l*512, poa, M_, 512, E_, 0);

        sample_kernel<<<(M_ * NH_ * 32) / 256, 256>>>();

        fg_gemm<64,64><<<dim3(E_/64, GM64), 256, SMEM64>>>(psam, pWoutF + l*sVal,
                                           b_out + l*E_, ptmp, M_, E_, E_, 0);
        ln_kernel<<<M_, E_>>>(px, ptmp, ln1_g + l*E_, ln1_b + l*E_, px, pxr,
                              (const float*)0, (float*)0);

        fg_gemm<128,128><<<dim3(DF_/128, GM128), 256, SMEM128>>>(pxr, pWff1F + l*sFf1,
                                            b_ff1 + l*DF_, phid, M_, DF_, E_, 1);
        fg_gemm<64,64><<<dim3(E_/64, GM64), 256, SMEM64>>>(phid, pWff2F + l*sFf2,
                                           b_ff2 + l*E_, ptmp, M_, E_, DF_, 0);

        if (l == NLAYERS_ - 1) {
            ln_kernel<<<M_, E_>>>(px, ptmp, ln2_g + l*E_, ln2_b + l*E_,
                                  (float*)d_out, (float*)0, (const float*)0, (float*)0);
        } else {
            ln_kernel<<<M_, E_>>>(px, ptmp, ln2_g + l*E_, ln2_b + l*E_,
                                  px, pxr, ppos, pq);
        }
    }
}

// round 9
// speedup vs baseline: 1.0339x; 1.0339x over previous
#include <cuda_runtime.h>
#include <math.h>
#include <stdint.h>

// ---------------- problem constants ----------------
#define B_ 2
#define E_ 256
#define NH_ 8
#define NL_ 4
#define NP_ 4
#define DF_ 1024
#define NLAYERS_ 6
#define HD_ 32
#define S_ 10548
#define M_ (B_*S_)          // 21096 query rows

__device__ __constant__ int c_LD[4] = {4, 2, 1, 1};
__device__ __constant__ int c_LH[4] = {48, 24, 12, 6};
__device__ __constant__ int c_LW[4] = {48, 24, 12, 6};

// ---------------- scratch (allocation-free) ----------------
__device__ float g_x  [M_*E_];
__device__ float g_xr [M_*E_];
__device__ float g_pos[M_*E_];
__device__ float g_q  [M_*E_];
__device__ float g_val[M_*E_];
__device__ float g_sam[M_*E_];
__device__ float g_tmp[M_*E_];
__device__ float g_oa [M_*512];    // packed: [0,384) offsets, [384,512) attn logits
__device__ float g_hid[M_*DF_];

// pre-rounded TRANSPOSED weights: [N rows][K cols], tf32-rounded
__device__ float g_WvalT[NLAYERS_*E_*E_];
__device__ float g_WqaT [NLAYERS_*512*E_];
__device__ float g_WoutT[NLAYERS_*E_*E_];
__device__ float g_Wff1T[NLAYERS_*DF_*E_];
__device__ float g_Wff2T[NLAYERS_*E_*DF_];
__device__ float g_bqa  [NLAYERS_*512];

// ---------------- tf32 helpers ----------------
__device__ __forceinline__ unsigned tf32_bits(float x)
{
    unsigned r;
    asm("cvt.rna.tf32.f32 %0, %1;\n" : "=r"(r) : "f"(x));
    return r;
}
__device__ __forceinline__ float tf32_round(float x)
{
    return __uint_as_float(tf32_bits(x));
}

__device__ __forceinline__ void mma_tf32(float c[4], const unsigned a[4], const unsigned b[2])
{
    asm volatile("mma.sync.aligned.m16n8k8.row.col.f32.tf32.tf32.f32 "
        "{%0,%1,%2,%3}, {%4,%5,%6,%7}, {%8,%9}, {%0,%1,%2,%3};\n"
        : "+f"(c[0]), "+f"(c[1]), "+f"(c[2]), "+f"(c[3])
        : "r"(a[0]), "r"(a[1]), "r"(a[2]), "r"(a[3]), "r"(b[0]), "r"(b[1]));
}

__device__ __forceinline__ void cp_async16(void* smem, const void* gmem, bool valid)
{
    unsigned saddr = (unsigned)__cvta_generic_to_shared(smem);
    int sz = valid ? 16 : 0;
    asm volatile("cp.async.cg.shared.global [%0], [%1], 16, %2;\n"
                 :: "r"(saddr), "l"(gmem), "r"(sz));
}
__device__ __forceinline__ void cp_commit() { asm volatile("cp.async.commit_group;\n"); }
template<int N> __device__ __forceinline__ void cp_wait() { asm volatile("cp.async.wait_group %0;\n" :: "n"(N)); }

#define LDSM_X4(r0,r1,r2,r3,addr) \
    asm volatile("ldmatrix.sync.aligned.m8n8.x4.shared.b16 {%0,%1,%2,%3}, [%4];\n" \
        : "=r"(r0), "=r"(r1), "=r"(r2), "=r"(r3) : "r"(addr))

// ---------------- weight transpose + round: src[K,N] -> dst[N,K] ----------------
__global__ void transpose_round(const float* __restrict__ src, float* __restrict__ dst,
                                int K, int N, int lsrc, int ldst, int rowOff)
{
    __shared__ float t[32][33];
    int n0 = blockIdx.x * 32;
    int k0 = blockIdx.y * 32;
    int l  = blockIdx.z;
    int tx = threadIdx.x, ty = threadIdx.y;
    t[ty][tx] = src[(size_t)l*lsrc + (size_t)(k0 + ty)*N + n0 + tx];
    __syncthreads();
    dst[(size_t)l*ldst + (size_t)(rowOff + n0 + ty)*K + k0 + tx] = tf32_round(t[tx][ty]);
}

__global__ void pack_bias_qa(const float* __restrict__ boff, const float* __restrict__ battn)
{
    int idx = blockIdx.x * blockDim.x + threadIdx.x;
    if (idx < NLAYERS_ * 512) {
        int l = idx >> 9, c = idx & 511;
        g_bqa[idx] = (c < 384) ? boff[l*384 + c] : battn[l*128 + (c - 384)];
    }
}

// ---------------- coalesced transposing init (per level) ----------------
__global__ void init_t_kernel(const float* __restrict__ f, const float* __restrict__ p,
                              const float* __restrict__ le_row, int n, int s0)
{
    __shared__ float tf[32][33];
    __shared__ float tp[32][33];
    int i0 = blockIdx.x * 32;
    int e0 = blockIdx.y * 32;
    int b  = blockIdx.z;
    int tx = threadIdx.x, ty = threadIdx.y;

    int ig = i0 + tx;
    int eg = e0 + ty;
    if (ig < n) {
        size_t src = (size_t)(b*E_ + eg) * n + ig;
        tf[ty][tx] = f[src];
        tp[ty][tx] = p[src];
    }
    __syncthreads();

    int iw = i0 + ty;
    int ew = e0 + tx;
    if (iw < n) {
        size_t dst = (size_t)(b*S_ + s0 + iw) * E_ + ew;
        float xv = tf[tx][ty];
        float pv = tp[tx][ty] + le_row[ew];
        g_x[dst]   = xv;
        g_xr[dst]  = tf32_round(xv);
        g_pos[dst] = pv;
        g_q[dst]   = tf32_round(xv + pv);
    }
}

// ---------------- tf32 mma GEMM: A and B(T) via cp.async + ldmatrix ----------
// C[M,N] = A[M,K] @ Wt[N,K]^T + bias. 256 threads, warps 2 rows x 4 cols.
// Both A and B smem tiles are K-major rows with stride 36 floats (conflict-free LDSM).
template<int BMt, int BNt>
__global__ void __launch_bounds__(256, (BMt==64 ? 4 : 2))
fg_gemm(const float* __restrict__ A, const float* __restrict__ Wt,
        const float* __restrict__ bias, float* __restrict__ C,
        int M, int N, int K, int mode)
{
    constexpr int MI   = BMt/32;       // m16 tiles per warp (warp m = BMt/2)
    constexpr int NI   = BNt/32;       // n8 tiles per warp (warp n = BNt/4)
    constexpr int ACH  = BMt/32;       // A 16B chunks per thread per stage
    constexpr int BCH  = BNt/32;       // B 16B chunks per thread per stage
    constexpr int STR  = 36;
    constexpr int A_FL = BMt*STR;
    constexpr int B_FL = BNt*STR;
    constexpr int STG  = A_FL + B_FL;

    extern __shared__ float smp[];

    int tid  = threadIdx.x;
    int lane = tid & 31;
    int wid  = tid >> 5;
    int bm = blockIdx.y * BMt;
    int bn = blockIdx.x * BNt;
    int wm = (wid >> 2) * (BMt/2);
    int wn = (wid & 3) * (BNt/4);

    float acc[MI][NI][4];
    #pragma unroll
    for (int mi = 0; mi < MI; mi++)
        #pragma unroll
        for (int ni = 0; ni < NI; ni++)
            #pragma unroll
            for (int j = 0; j < 4; j++) acc[mi][ni][j] = 0.f;

    // cp.async maps (rows of 32 floats = 8 chunks)
    int arow[ACH], ac[ACH]; bool aval[ACH];
    #pragma unroll
    for (int i = 0; i < ACH; i++) {
        int idx = tid + i*256; arow[i] = idx >> 3; ac[i] = idx & 7;
        aval[i] = (bm + arow[i]) < M;
    }
    int brow[BCH], bc[BCH];
    #pragma unroll
    for (int i = 0; i < BCH; i++) { int idx = tid + i*256; brow[i] = idx >> 3; bc[i] = idx & 7; }

    int nkt = K / 32;

    // ldmatrix lane constants
    int mt = lane >> 3;
    int arb  = (mt & 1)*8 + (lane & 7);   // A: row-within-warp-tile
    int ako  = (mt >> 1)*4;               // A: k offset
    int brb  = (mt >> 1)*8 + (lane & 7);  // B: n-row within 16-row pair
    int bko  = (mt & 1)*4;                // B: k offset (half)
    unsigned smem_u32 = (unsigned)__cvta_generic_to_shared(smp);

    auto load_stage = [&](int slot, int kg) {
        float* As = smp + slot*STG;
        float* Bs = As + A_FL;
        #pragma unroll
        for (int i = 0; i < ACH; i++)
            cp_async16(As + arow[i]*STR + ac[i]*4,
                       A + (size_t)(aval[i] ? (bm + arow[i]) : 0) * K + kg + ac[i]*4, aval[i]);
        #pragma unroll
        for (int i = 0; i < BCH; i++)
            cp_async16(Bs + brow[i]*STR + bc[i]*4,
                       Wt + (size_t)(bn + brow[i]) * K + kg + bc[i]*4, true);
    };

    // prologue: stages 0 and 1
    load_stage(0, 0);
    cp_commit();
    if (nkt > 1) load_stage(1, 32);
    cp_commit();

    for (int kt = 0; kt < nkt; kt++) {
        int st = kt % 3;
        if (kt + 2 < nkt) load_stage((kt + 2) % 3, (kt + 2) * 32);
        cp_commit();
        cp_wait<2>();
        __syncthreads();

        unsigned abase = smem_u32 + (unsigned)(st*STG)*4u
                       + (unsigned)((wm + arb)*STR + ako)*4u;
        unsigned bbase = smem_u32 + (unsigned)(st*STG + A_FL)*4u
                       + (unsigned)((wn + brb)*STR + bko)*4u;

        #pragma unroll
        for (int ks = 0; ks < 4; ks++) {
            unsigned af[MI][4], bf[NI][2];
            #pragma unroll
            for (int mi = 0; mi < MI; mi++) {
                LDSM_X4(af[mi][0], af[mi][1], af[mi][2], af[mi][3],
                        abase + (unsigned)((mi*16*STR + ks*8)*4));
            }
            #pragma unroll
            for (int nb = 0; nb < NI/2; nb++) {
                LDSM_X4(bf[2*nb][0], bf[2*nb][1], bf[2*nb+1][0], bf[2*nb+1][1],
                        bbase + (unsigned)((nb*16*STR + ks*8)*4));
            }
            #pragma unroll
            for (int mi = 0; mi < MI; mi++)
                #pragma unroll
                for (int ni = 0; ni < NI; ni++)
                    mma_tf32(acc[mi][ni], af[mi], bf[ni]);
        }
        __syncthreads();
    }

    // epilogue
    int qq = lane >> 2, rr = lane & 3;
    #pragma unroll
    for (int mi = 0; mi < MI; mi++) {
        #pragma unroll
        for (int ni = 0; ni < NI; ni++) {
            int row = bm + wm + mi*16 + qq;
            int col = bn + wn + ni*8 + rr*2;
            float bx = bias[col], by = bias[col+1];
            if (row < M) {
                float v0 = acc[mi][ni][0] + bx;
                float v1 = acc[mi][ni][1] + by;
                if (mode == 1) { v0 = tf32_round(fmaxf(v0, 0.f)); v1 = tf32_round(fmaxf(v1, 0.f)); }
                *(float2*)&C[(size_t)row * N + col] = make_float2(v0, v1);
            }
            if (row + 8 < M) {
                float v2 = acc[mi][ni][2] + bx;
                float v3 = acc[mi][ni][3] + by;
                if (mode == 1) { v2 = tf32_round(fmaxf(v2, 0.f)); v3 = tf32_round(fmaxf(v3, 0.f)); }
                *(float2*)&C[(size_t)(row + 8) * N + col] = make_float2(v2, v3);
            }
        }
    }
}

// ---------------- deformable sampling, float4-vectorized ----------------
__global__ void sample_kernel()
{
    int warpIdx = (blockIdx.x * blockDim.x + threadIdx.x) >> 5;
    int lane  = threadIdx.x & 31;
    if (warpIdx >= M_ * NH_) return;
    int h  = warpIdx / M_;
    int bs = warpIdx - h * M_;
    int b  = bs / S_;
    int s  = bs % S_;
    int eg = lane & 7;
    int pg = lane >> 3;

    int lvl_q, iq;
    if (s < 9216)       { lvl_q = 0; iq = s;         }
    else if (s < 10368) { lvl_q = 1; iq = s - 9216;  }
    else if (s < 10512) { lvl_q = 2; iq = s - 10368; }
    else                { lvl_q = 3; iq = s - 10512; }
    int Wq = c_LW[lvl_q], Hq = c_LH[lvl_q], Dq = c_LD[lvl_q];
    int xq = iq % Wq;
    int t  = iq / Wq;
    int yq = t % Hq;
    int zq = t / Hq;
    float rx = (xq + 0.5f) / (float)Wq;
    float ry = (yq + 0.5f) / (float)Hq;
    float rz = (zq + 0.5f) / (float)Dq;

    const float4* lg4 = (const float4*)(g_oa + (size_t)bs * 512 + 384 + h * 16);
    float lv[16];
    {
        float4 v0 = lg4[0], v1 = lg4[1], v2 = lg4[2], v3 = lg4[3];
        lv[0]=v0.x; lv[1]=v0.y; lv[2]=v0.z; lv[3]=v0.w;
        lv[4]=v1.x; lv[5]=v1.y; lv[6]=v1.z; lv[7]=v1.w;
        lv[8]=v2.x; lv[9]=v2.y; lv[10]=v2.z; lv[11]=v2.w;
        lv[12]=v3.x; lv[13]=v3.y; lv[14]=v3.z; lv[15]=v3.w;
    }
    float mx = -1e30f;
    #pragma unroll
    for (int j = 0; j < 16; j++) mx = fmaxf(mx, lv[j]);
    float ssum = 0.f;
    #pragma unroll
    for (int j = 0; j < 16; j++) { lv[j] = __expf(lv[j] - mx); ssum += lv[j]; }
    float inv = 1.f / ssum;

    const float* offp = g_oa + (size_t)bs * 512 + h * (NL_*NP_*3);

    const int LDc[4]  = {4, 2, 1, 1};
    const int LHc[4]  = {48, 24, 12, 6};
    const int LWc[4]  = {48, 24, 12, 6};
    const int LS0c[4] = {0, 9216, 10368, 10512};

    float4 acc = make_float4(0.f, 0.f, 0.f, 0.f);

    #pragma unroll
    for (int lvl = 0; lvl < 4; lvl++) {
        const int Dl = LDc[lvl], Hl = LHc[lvl], Wl = LWc[lvl];
        const float* vb = g_val + ((size_t)b * S_ + LS0c[lvl]) * E_ + h * HD_ + eg * 4;

        float aw = lv[lvl*4 + pg] * inv;
        float ox = offp[lvl*12 + pg*3 + 0];
        float oy = offp[lvl*12 + pg*3 + 1];
        float oz = offp[lvl*12 + pg*3 + 2];
        float cx = rx * (float)Wl + ox - 0.5f;
        float cy = ry * (float)Hl + oy - 0.5f;
        float cz = rz * (float)Dl + oz - 0.5f;
        float xf = floorf(cx), yf = floorf(cy), zf = floorf(cz);
        float fx = cx - xf, fy = cy - yf, fz = cz - zf;
        int x0 = (int)xf, y0 = (int)yf, z0 = (int)zf;

        #pragma unroll
        for (int dz = 0; dz < 2; dz++) {
            int iz = z0 + dz;
            float wz = dz ? fz : 1.f - fz;
            bool vz = (iz >= 0) & (iz < Dl);
            int cz_i = min(max(iz, 0), Dl - 1);
            #pragma unroll
            for (int dy = 0; dy < 2; dy++) {
                int iy = y0 + dy;
                float wy = dy ? fy : 1.f - fy;
                bool vy = (iy >= 0) & (iy < Hl);
                int cy_i = min(max(iy, 0), Hl - 1);
                #pragma unroll
                for (int dx = 0; dx < 2; dx++) {
                    int ix = x0 + dx;
                    float wx = dx ? fx : 1.f - fx;
                    bool vx = (ix >= 0) & (ix < Wl);
                    int cx_i = min(max(ix, 0), Wl - 1);
                    float wgt = (vz & vy & vx) ? (aw * wx * wy * wz) : 0.f;
                    int idx = (cz_i*Hl + cy_i)*Wl + cx_i;
                    float4 v = *(const float4*)(vb + (size_t)idx * E_);
                    acc.x += wgt * v.x;
                    acc.y += wgt * v.y;
                    acc.z += wgt * v.z;
                    acc.w += wgt * v.w;
                }
            }
        }
    }

    #pragma unroll
    for (int o = 8; o <= 16; o <<= 1) {
        acc.x += __shfl_xor_sync(0xFFFFFFFFu, acc.x, o);
        acc.y += __shfl_xor_sync(0xFFFFFFFFu, acc.y, o);
        acc.z += __shfl_xor_sync(0xFFFFFFFFu, acc.z, o);
        acc.w += __shfl_xor_sync(0xFFFFFFFFu, acc.w, o);
    }

    if (lane < 8) {
        float4 o4;
        o4.x = tf32_round(acc.x);
        o4.y = tf32_round(acc.y);
        o4.z = tf32_round(acc.z);
        o4.w = tf32_round(acc.w);
        *(float4*)(g_sam + (size_t)bs * E_ + h * HD_ + lane * 4) = o4;
    }
}

// ---------------- fused residual + LayerNorm (+ rounded copies) -------------
__device__ __forceinline__ float warp_sum(float v)
{
    #pragma unroll
    for (int o = 16; o > 0; o >>= 1) v += __shfl_xor_sync(0xFFFFFFFFu, v, o);
    return v;
}

__global__ void ln_kernel(const float* __restrict__ x, const float* __restrict__ r,
                          const float* __restrict__ g, const float* __restrict__ be,
                          float* __restrict__ out, float* __restrict__ outr,
                          const float* __restrict__ pos, float* __restrict__ qout)
{
    int row = blockIdx.x;
    int e = threadIdx.x;
    size_t base = (size_t)row * E_;
    float v = x[base + e] + r[base + e];
    __shared__ float sh[8];
    float ws = warp_sum(v);
    int w = e >> 5, ln = e & 31;
    if (ln == 0) sh[w] = ws;
    __syncthreads();
    float mean = 0.f;
    #pragma unroll
    for (int i = 0; i < 8; i++) mean += sh[i];
    mean *= (1.f / E_);
    __syncthreads();
    float d = v - mean;
    float ws2 = warp_sum(d * d);
    if (ln == 0) sh[w] = ws2;
    __syncthreads();
    float var = 0.f;
    #pragma unroll
    for (int i = 0; i < 8; i++) var += sh[i];
    var *= (1.f / E_);
    float y = d * rsqrtf(var + 1e-5f) * g[e] + be[e];
    out[base + e] = y;
    if (outr) outr[base + e] = tf32_round(y);
    if (qout) qout[base + e] = tf32_round(y + pos[base + e]);
}

// ---------------- host launcher ----------------
#define SMEM128 (3*(128*36 + 128*36)*4)   // 110592
#define SMEM64  (3*(64*36 + 64*36)*4)     // 55296

extern "C" void kernel_launch(void* const* d_in, const int* in_sizes, int n_in,
                              void* d_out, int out_size)
{
    (void)in_sizes; (void)n_in; (void)out_size;
    const float* f0 = (const float*)d_in[0];
    const float* p0 = (const float*)d_in[1];
    const float* f1 = (const float*)d_in[2];
    const float* p1 = (const float*)d_in[3];
    const float* f2 = (const float*)d_in[4];
    const float* p2 = (const float*)d_in[5];
    const float* f3 = (const float*)d_in[6];
    const float* p3 = (const float*)d_in[7];
    const float* le = (const float*)d_in[8];
    const float* W_off  = (const float*)d_in[9];
    const float* b_off  = (const float*)d_in[10];
    const float* W_attn = (const float*)d_in[11];
    const float* b_attn = (const float*)d_in[12];
    const float* W_val  = (const float*)d_in[13];
    const float* b_val  = (const float*)d_in[14];
    const float* W_out  = (const float*)d_in[15];
    const float* b_out  = (const float*)d_in[16];
    const float* ln1_g  = (const float*)d_in[17];
    const float* ln1_b  = (const float*)d_in[18];
    const float* W_ff1  = (const float*)d_in[19];
    const float* b_ff1  = (const float*)d_in[20];
    const float* W_ff2  = (const float*)d_in[21];
    const float* b_ff2  = (const float*)d_in[22];
    const float* ln2_g  = (const float*)d_in[23];
    const float* ln2_b  = (const float*)d_in[24];

    float *px, *pxr, *ppos, *pq, *pval, *psam, *ptmp, *phid, *poa, *pbqa;
    float *pWvalT, *pWqaT, *pWoutT, *pWff1T, *pWff2T;
    cudaGetSymbolAddress((void**)&px,     g_x);
    cudaGetSymbolAddress((void**)&pxr,    g_xr);
    cudaGetSymbolAddress((void**)&ppos,   g_pos);
    cudaGetSymbolAddress((void**)&pq,     g_q);
    cudaGetSymbolAddress((void**)&pval,   g_val);
    cudaGetSymbolAddress((void**)&psam,   g_sam);
    cudaGetSymbolAddress((void**)&ptmp,   g_tmp);
    cudaGetSymbolAddress((void**)&phid,   g_hid);
    cudaGetSymbolAddress((void**)&poa,    g_oa);
    cudaGetSymbolAddress((void**)&pWvalT, g_WvalT);
    cudaGetSymbolAddress((void**)&pWqaT,  g_WqaT);
    cudaGetSymbolAddress((void**)&pWoutT, g_WoutT);
    cudaGetSymbolAddress((void**)&pWff1T, g_Wff1T);
    cudaGetSymbolAddress((void**)&pWff2T, g_Wff2T);
    cudaGetSymbolAddress((void**)&pbqa,   g_bqa);

    cudaFuncSetAttribute(fg_gemm<128,128>, cudaFuncAttributeMaxDynamicSharedMemorySize, SMEM128);
    cudaFuncSetAttribute(fg_gemm<64,64>,   cudaFuncAttributeMaxDynamicSharedMemorySize, SMEM64);

    // weight transpose + round (+ qa packing)
    {
        dim3 tb(32, 32);
        transpose_round<<<dim3(256/32, 256/32, NLAYERS_), tb>>>(W_val, pWvalT, 256, 256, 256*256, 256*256, 0);
        transpose_round<<<dim3(256/32, 256/32, NLAYERS_), tb>>>(W_out, pWoutT, 256, 256, 256*256, 256*256, 0);
        transpose_round<<<dim3(1024/32, 256/32, NLAYERS_), tb>>>(W_ff1, pWff1T, 256, 1024, 256*1024, 1024*256, 0);
        transpose_round<<<dim3(256/32, 1024/32, NLAYERS_), tb>>>(W_ff2, pWff2T, 1024, 256, 1024*256, 256*1024, 0);
        transpose_round<<<dim3(384/32, 256/32, NLAYERS_), tb>>>(W_off, pWqaT, 256, 384, 256*384, 512*256, 0);
        transpose_round<<<dim3(128/32, 256/32, NLAYERS_), tb>>>(W_attn, pWqaT, 256, 128, 256*128, 512*256, 384);
        pack_bias_qa<<<(NLAYERS_*512 + 255)/256, 256>>>(b_off, b_attn);
    }

    // transposing init, one launch per level
    {
        dim3 blk(32, 32);
        init_t_kernel<<<dim3(288, 8, B_), blk>>>(f0, p0, le + 0*E_, 9216, 0);
        init_t_kernel<<<dim3( 36, 8, B_), blk>>>(f1, p1, le + 1*E_, 1152, 9216);
        init_t_kernel<<<dim3(  5, 8, B_), blk>>>(f2, p2, le + 2*E_,  144, 10368);
        init_t_kernel<<<dim3(  2, 8, B_), blk>>>(f3, p3, le + 3*E_,   36, 10512);
    }

    const int GM64  = (M_ + 63) / 64;    // 330
    const int GM128 = (M_ + 127) / 128;  // 165

    for (int l = 0; l < NLAYERS_; l++) {
        fg_gemm<64,64><<<dim3(E_/64, GM64), 256, SMEM64>>>(pxr, pWvalT + (size_t)l*E_*E_,
                                           b_val + l*E_, pval, M_, E_, E_, 0);
        fg_gemm<128,128><<<dim3(512/128, GM128), 256, SMEM128>>>(pq, pWqaT + (size_t)l*512*E_,
                                            pbqa + l*512, poa, M_, 512, E_, 0);

        sample_kernel<<<(M_ * NH_ * 32) / 256, 256>>>();

        fg_gemm<64,64><<<dim3(E_/64, GM64), 256, SMEM64>>>(psam, pWoutT + (size_t)l*E_*E_,
                                           b_out + l*E_, ptmp, M_, E_, E_, 0);
        ln_kernel<<<M_, E_>>>(px, ptmp, ln1_g + l*E_, ln1_b + l*E_, px, pxr,
                              (const float*)0, (float*)0);

        fg_gemm<128,128><<<dim3(DF_/128, GM128), 256, SMEM128>>>(pxr, pWff1T + (size_t)l*E_*DF_,
                                            b_ff1 + l*DF_, phid, M_, DF_, E_, 1);
        fg_gemm<64,64><<<dim3(E_/64, GM64), 256, SMEM64>>>(phid, pWff2T + (size_t)l*E_*DF_,
                                           b_ff2 + l*E_, ptmp, M_, E_, DF_, 0);

        if (l == NLAYERS_ - 1) {
            ln_kernel<<<M_, E_>>>(px, ptmp, ln2_g + l*E_, ln2_b + l*E_,
                                  (float*)d_out, (float*)0, (const float*)0, (float*)0);
        } else {
            ln_kernel<<<M_, E_>>>(px, ptmp, ln2_g + l*E_, ln2_b + l*E_,
                                  px, pxr, ppos, pq);
        }
    }
}

// round 10
// speedup vs baseline: 1.1167x; 1.0801x over previous
#include <cuda_runtime.h>
#include <math.h>
#include <stdint.h>

// ---------------- problem constants ----------------
#define B_ 2
#define E_ 256
#define NH_ 8
#define NL_ 4
#define NP_ 4
#define DF_ 1024
#define NLAYERS_ 6
#define HD_ 32
#define S_ 10548
#define M_ (B_*S_)          // 21096 query rows

__device__ __constant__ int c_LD[4] = {4, 2, 1, 1};
__device__ __constant__ int c_LH[4] = {48, 24, 12, 6};
__device__ __constant__ int c_LW[4] = {48, 24, 12, 6};

// ---------------- scratch (allocation-free) ----------------
__device__ float g_x  [M_*E_];
__device__ float g_xr [M_*E_];
__device__ float g_pos[M_*E_];
__device__ float g_q  [M_*E_];
__device__ float g_val[M_*E_];
__device__ float g_sam[M_*E_];
__device__ float g_tmp[M_*E_];
__device__ float g_oa [M_*512];    // packed: [0,384) offsets, [384,512) attn logits
__device__ float g_hid[M_*DF_];

// pre-rounded packed weights [K,N] row-major
__device__ float g_Wval[NLAYERS_*E_*E_];
__device__ float g_Wqa [NLAYERS_*E_*512];
__device__ float g_Wout[NLAYERS_*E_*E_];
__device__ float g_Wff1[NLAYERS_*E_*DF_];
__device__ float g_Wff2[NLAYERS_*DF_*E_];
__device__ float g_bqa [NLAYERS_*512];

// ---------------- tf32 helpers ----------------
__device__ __forceinline__ unsigned tf32_bits(float x)
{
    unsigned r;
    asm("cvt.rna.tf32.f32 %0, %1;\n" : "=r"(r) : "f"(x));
    return r;
}
__device__ __forceinline__ float tf32_round(float x)
{
    return __uint_as_float(tf32_bits(x));
}

__device__ __forceinline__ void mma_tf32(float c[4], const unsigned a[4], const unsigned b[2])
{
    asm volatile("mma.sync.aligned.m16n8k8.row.col.f32.tf32.tf32.f32 "
        "{%0,%1,%2,%3}, {%4,%5,%6,%7}, {%8,%9}, {%0,%1,%2,%3};\n"
        : "+f"(c[0]), "+f"(c[1]), "+f"(c[2]), "+f"(c[3])
        : "r"(a[0]), "r"(a[1]), "r"(a[2]), "r"(a[3]), "r"(b[0]), "r"(b[1]));
}

__device__ __forceinline__ void cp_async16(void* smem, const void* gmem, bool valid)
{
    unsigned saddr = (unsigned)__cvta_generic_to_shared(smem);
    int sz = valid ? 16 : 0;
    asm volatile("cp.async.cg.shared.global [%0], [%1], 16, %2;\n"
                 :: "r"(saddr), "l"(gmem), "r"(sz));
}
__device__ __forceinline__ void cp_commit() { asm volatile("cp.async.commit_group;\n"); }
template<int N> __device__ __forceinline__ void cp_wait() { asm volatile("cp.async.wait_group %0;\n" :: "n"(N)); }

#define LDSM_X4(r0,r1,r2,r3,addr) \
    asm volatile("ldmatrix.sync.aligned.m8n8.x4.shared.b16 {%0,%1,%2,%3}, [%4];\n" \
        : "=r"(r0), "=r"(r1), "=r"(r2), "=r"(r3) : "r"(addr))

// ---------------- weight pack / round kernels ----------------
__global__ void roundcopy_kernel(float* __restrict__ dst, const float* __restrict__ src, int n)
{
    int i = blockIdx.x * blockDim.x + threadIdx.x;
    if (i < n) dst[i] = tf32_round(src[i]);
}

__global__ void pack_qa_kernel(const float* __restrict__ Woff, const float* __restrict__ Wattn,
                               const float* __restrict__ boff, const float* __restrict__ battn)
{
    int idx = blockIdx.x * blockDim.x + threadIdx.x;
    int tot = NLAYERS_ * E_ * 512;
    if (idx < tot) {
        int l = idx / (E_ * 512);
        int rem = idx - l * E_ * 512;
        int k = rem >> 9;
        int c = rem & 511;
        float v = (c < 384) ? Woff[(size_t)l*E_*384 + k*384 + c]
                            : Wattn[(size_t)l*E_*128 + k*128 + (c - 384)];
        g_Wqa[idx] = tf32_round(v);
    }
    if (idx < NLAYERS_ * 512) {
        int l = idx >> 9;
        int c = idx & 511;
        g_bqa[idx] = (c < 384) ? boff[l*384 + c] : battn[l*128 + (c - 384)];
    }
}

// ---------------- coalesced transposing init (per level) ----------------
__global__ void init_t_kernel(const float* __restrict__ f, const float* __restrict__ p,
                              const float* __restrict__ le_row, int n, int s0)
{
    __shared__ float tf[32][33];
    __shared__ float tp[32][33];
    int i0 = blockIdx.x * 32;
    int e0 = blockIdx.y * 32;
    int b  = blockIdx.z;
    int tx = threadIdx.x, ty = threadIdx.y;

    int ig = i0 + tx;
    int eg = e0 + ty;
    if (ig < n) {
        size_t src = (size_t)(b*E_ + eg) * n + ig;
        tf[ty][tx] = f[src];
        tp[ty][tx] = p[src];
    }
    __syncthreads();

    int iw = i0 + ty;
    int ew = e0 + tx;
    if (iw < n) {
        size_t dst = (size_t)(b*S_ + s0 + iw) * E_ + ew;
        float xv = tf[tx][ty];
        float pv = tp[tx][ty] + le_row[ew];
        g_x[dst]   = xv;
        g_xr[dst]  = tf32_round(xv);
        g_pos[dst] = pv;
        g_q[dst]   = tf32_round(xv + pv);
    }
}

// ---------------- tf32 tensor-core GEMM, 3-stage cp.async, ldmatrix A ------
template<int BMt, int BNt>
__global__ void __launch_bounds__(256, (BMt==64 ? 4 : 2))
mma_gemm(const float* __restrict__ A, const float* __restrict__ W,
         const float* __restrict__ bias, float* __restrict__ C,
         int M, int N, int K, int mode)
{
    constexpr int MI   = BMt/32;
    constexpr int NI   = BNt/32;
    constexpr int ACH  = BMt/32;
    constexpr int BCH  = BNt/32;
    constexpr int CPR  = BNt/4;
    constexpr int ASTR = 36;
    constexpr int BSTR = BNt + 8;
    constexpr int A_FL = BMt*ASTR;
    constexpr int B_FL = 32*BSTR;
    constexpr int STG  = A_FL + B_FL;

    extern __shared__ float smp[];

    int tid  = threadIdx.x;
    int lane = tid & 31;
    int wid  = tid >> 5;
    int bm = blockIdx.y * BMt;
    int bn = blockIdx.x * BNt;
    int wm = (wid >> 2) * (BMt/2);
    int wn = (wid & 3) * (BNt/4);
    int q = lane >> 2;
    int r = lane & 3;

    float acc[MI][NI][4];
    #pragma unroll
    for (int mi = 0; mi < MI; mi++)
        #pragma unroll
        for (int ni = 0; ni < NI; ni++)
            #pragma unroll
            for (int j = 0; j < 4; j++) acc[mi][ni][j] = 0.f;

    int arow[ACH], ac[ACH]; bool aval[ACH];
    #pragma unroll
    for (int i = 0; i < ACH; i++) {
        int idx = tid + i*256; arow[i] = idx >> 3; ac[i] = idx & 7;
        aval[i] = (bm + arow[i]) < M;
    }
    int brow[BCH], bc[BCH];
    #pragma unroll
    for (int i = 0; i < BCH; i++) { int idx = tid + i*256; brow[i] = idx / CPR; bc[i] = idx % CPR; }

    int nkt = K / 32;

    int mt = lane >> 3;
    int rbase = (mt & 1)*8 + (lane & 7);
    int koff = (mt >> 1)*4;
    unsigned smem_u32 = (unsigned)__cvta_generic_to_shared(smp);

    {
        float* As = smp;
        float* Bs = smp + A_FL;
        #pragma unroll
        for (int i = 0; i < ACH; i++)
            cp_async16(As + arow[i]*ASTR + ac[i]*4,
                       A + (size_t)(aval[i] ? (bm + arow[i]) : 0) * K + ac[i]*4, aval[i]);
        #pragma unroll
        for (int i = 0; i < BCH; i++)
            cp_async16(Bs + brow[i]*BSTR + bc[i]*4,
                       W + (size_t)brow[i] * N + bn + bc[i]*4, true);
        cp_commit();
        if (nkt > 1) {
            float* As1 = smp + STG;
            float* Bs1 = As1 + A_FL;
            #pragma unroll
            for (int i = 0; i < ACH; i++)
                cp_async16(As1 + arow[i]*ASTR + ac[i]*4,
                           A + (size_t)(aval[i] ? (bm + arow[i]) : 0) * K + 32 + ac[i]*4, aval[i]);
            #pragma unroll
            for (int i = 0; i < BCH; i++)
                cp_async16(Bs1 + brow[i]*BSTR + bc[i]*4,
                           W + (size_t)(32 + brow[i]) * N + bn + bc[i]*4, true);
        }
        cp_commit();
    }

    for (int kt = 0; kt < nkt; kt++) {
        int st = kt % 3;
        if (kt + 2 < nkt) {
            int s2 = (kt + 2) % 3;
            float* As = smp + s2*STG;
            float* Bs = As + A_FL;
            int kg = (kt + 2) * 32;
            #pragma unroll
            for (int i = 0; i < ACH; i++)
                cp_async16(As + arow[i]*ASTR + ac[i]*4,
                           A + (size_t)(aval[i] ? (bm + arow[i]) : 0) * K + kg + ac[i]*4, aval[i]);
            #pragma unroll
            for (int i = 0; i < BCH; i++)
                cp_async16(Bs + brow[i]*BSTR + bc[i]*4,
                           W + (size_t)(kg + brow[i]) * N + bn + bc[i]*4, true);
        }
        cp_commit();
        cp_wait<2>();
        __syncthreads();

        const float* Bs = smp + st*STG + A_FL;
        unsigned abase = smem_u32 + (unsigned)(st*STG)*4u
                       + (unsigned)((wm + rbase)*ASTR + koff)*4u;

        #pragma unroll
        for (int ks = 0; ks < 4; ks++) {
            unsigned af[MI][4], bf[NI][2];
            #pragma unroll
            for (int mi = 0; mi < MI; mi++) {
                LDSM_X4(af[mi][0], af[mi][1], af[mi][2], af[mi][3],
                        abase + (unsigned)((mi*16*ASTR + ks*8)*4));
            }
            #pragma unroll
            for (int ni = 0; ni < NI; ni++) {
                bf[ni][0] = __float_as_uint(Bs[(ks*8 + r    )*BSTR + wn + ni*8 + q]);
                bf[ni][1] = __float_as_uint(Bs[(ks*8 + r + 4)*BSTR + wn + ni*8 + q]);
            }
            #pragma unroll
            for (int mi = 0; mi < MI; mi++)
                #pragma unroll
                for (int ni = 0; ni < NI; ni++)
                    mma_tf32(acc[mi][ni], af[mi], bf[ni]);
        }
        __syncthreads();
    }

    #pragma unroll
    for (int mi = 0; mi < MI; mi++) {
        #pragma unroll
        for (int ni = 0; ni < NI; ni++) {
            int row = bm + wm + mi*16 + q;
            int col = bn + wn + ni*8 + r*2;
            float bx = bias[col], by = bias[col+1];
            if (row < M) {
                float v0 = acc[mi][ni][0] + bx;
                float v1 = acc[mi][ni][1] + by;
                if (mode == 1) { v0 = tf32_round(fmaxf(v0, 0.f)); v1 = tf32_round(fmaxf(v1, 0.f)); }
                *(float2*)&C[(size_t)row * N + col] = make_float2(v0, v1);
            }
            if (row + 8 < M) {
                float v2 = acc[mi][ni][2] + bx;
                float v3 = acc[mi][ni][3] + by;
                if (mode == 1) { v2 = tf32_round(fmaxf(v2, 0.f)); v3 = tf32_round(fmaxf(v3, 0.f)); }
                *(float2*)&C[(size_t)(row + 8) * N + col] = make_float2(v2, v3);
            }
        }
    }
}

// ---------------- deformable sampling, float4-vectorized ----------------
__global__ void sample_kernel()
{
    int warpIdx = (blockIdx.x * blockDim.x + threadIdx.x) >> 5;
    int lane  = threadIdx.x & 31;
    if (warpIdx >= M_ * NH_) return;
    int h  = warpIdx / M_;
    int bs = warpIdx - h * M_;
    int b  = bs / S_;
    int s  = bs % S_;
    int eg = lane & 7;
    int pg = lane >> 3;

    int lvl_q, iq;
    if (s < 9216)       { lvl_q = 0; iq = s;         }
    else if (s < 10368) { lvl_q = 1; iq = s - 9216;  }
    else if (s < 10512) { lvl_q = 2; iq = s - 10368; }
    else                { lvl_q = 3; iq = s - 10512; }
    int Wq = c_LW[lvl_q], Hq = c_LH[lvl_q], Dq = c_LD[lvl_q];
    int xq = iq % Wq;
    int t  = iq / Wq;
    int yq = t % Hq;
    int zq = t / Hq;
    float rx = (xq + 0.5f) / (float)Wq;
    float ry = (yq + 0.5f) / (float)Hq;
    float rz = (zq + 0.5f) / (float)Dq;

    const float4* lg4 = (const float4*)(g_oa + (size_t)bs * 512 + 384 + h * 16);
    float lv[16];
    {
        float4 v0 = lg4[0], v1 = lg4[1], v2 = lg4[2], v3 = lg4[3];
        lv[0]=v0.x; lv[1]=v0.y; lv[2]=v0.z; lv[3]=v0.w;
        lv[4]=v1.x; lv[5]=v1.y; lv[6]=v1.z; lv[7]=v1.w;
        lv[8]=v2.x; lv[9]=v2.y; lv[10]=v2.z; lv[11]=v2.w;
        lv[12]=v3.x; lv[13]=v3.y; lv[14]=v3.z; lv[15]=v3.w;
    }
    float mx = -1e30f;
    #pragma unroll
    for (int j = 0; j < 16; j++) mx = fmaxf(mx, lv[j]);
    float ssum = 0.f;
    #pragma unroll
    for (int j = 0; j < 16; j++) { lv[j] = __expf(lv[j] - mx); ssum += lv[j]; }
    float inv = 1.f / ssum;

    const float* offp = g_oa + (size_t)bs * 512 + h * (NL_*NP_*3);

    const int LDc[4]  = {4, 2, 1, 1};
    const int LHc[4]  = {48, 24, 12, 6};
    const int LWc[4]  = {48, 24, 12, 6};
    const int LS0c[4] = {0, 9216, 10368, 10512};

    float4 acc = make_float4(0.f, 0.f, 0.f, 0.f);

    #pragma unroll
    for (int lvl = 0; lvl < 4; lvl++) {
        const int Dl = LDc[lvl], Hl = LHc[lvl], Wl = LWc[lvl];
        const float* vb = g_val + ((size_t)b * S_ + LS0c[lvl]) * E_ + h * HD_ + eg * 4;

        float aw = lv[lvl*4 + pg] * inv;
        float ox = offp[lvl*12 + pg*3 + 0];
        float oy = offp[lvl*12 + pg*3 + 1];
        float oz = offp[lvl*12 + pg*3 + 2];
        float cx = rx * (float)Wl + ox - 0.5f;
        float cy = ry * (float)Hl + oy - 0.5f;
        float cz = rz * (float)Dl + oz - 0.5f;
        float xf = floorf(cx), yf = floorf(cy), zf = floorf(cz);
        float fx = cx - xf, fy = cy - yf, fz = cz - zf;
        int x0 = (int)xf, y0 = (int)yf, z0 = (int)zf;

        #pragma unroll
        for (int dz = 0; dz < 2; dz++) {
            int iz = z0 + dz;
            float wz = dz ? fz : 1.f - fz;
            bool vz = (iz >= 0) & (iz < Dl);
            int cz_i = min(max(iz, 0), Dl - 1);
            #pragma unroll
            for (int dy = 0; dy < 2; dy++) {
                int iy = y0 + dy;
                float wy = dy ? fy : 1.f - fy;
                bool vy = (iy >= 0) & (iy < Hl);
                int cy_i = min(max(iy, 0), Hl - 1);
                #pragma unroll
                for (int dx = 0; dx < 2; dx++) {
                    int ix = x0 + dx;
                    float wx = dx ? fx : 1.f - fx;
                    bool vx = (ix >= 0) & (ix < Wl);
                    int cx_i = min(max(ix, 0), Wl - 1);
                    float wgt = (vz & vy & vx) ? (aw * wx * wy * wz) : 0.f;
                    int idx = (cz_i*Hl + cy_i)*Wl + cx_i;
                    float4 v = *(const float4*)(vb + (size_t)idx * E_);
                    acc.x += wgt * v.x;
                    acc.y += wgt * v.y;
                    acc.z += wgt * v.z;
                    acc.w += wgt * v.w;
                }
            }
        }
    }

    #pragma unroll
    for (int o = 8; o <= 16; o <<= 1) {
        acc.x += __shfl_xor_sync(0xFFFFFFFFu, acc.x, o);
        acc.y += __shfl_xor_sync(0xFFFFFFFFu, acc.y, o);
        acc.z += __shfl_xor_sync(0xFFFFFFFFu, acc.z, o);
        acc.w += __shfl_xor_sync(0xFFFFFFFFu, acc.w, o);
    }

    if (lane < 8) {
        float4 o4;
        o4.x = tf32_round(acc.x);
        o4.y = tf32_round(acc.y);
        o4.z = tf32_round(acc.z);
        o4.w = tf32_round(acc.w);
        *(float4*)(g_sam + (size_t)bs * E_ + h * HD_ + lane * 4) = o4;
    }
}

// ---------------- fused residual + LayerNorm: warp-per-row, 8 rows/block ----
// Each lane owns 8 elements: float4 at lane*4 and float4 at 128 + lane*4.
__global__ void __launch_bounds__(256)
ln8_kernel(const float* __restrict__ x, const float* __restrict__ r,
           const float* __restrict__ g, const float* __restrict__ be,
           float* __restrict__ out, float* __restrict__ outr,
           const float* __restrict__ pos, float* __restrict__ qout)
{
    int wid  = threadIdx.x >> 5;
    int lane = threadIdx.x & 31;
    int row  = blockIdx.x * 8 + wid;   // M_ = 21096 = 2637 * 8
    size_t base = (size_t)row * E_;
    int c0 = lane * 4;
    int c1 = 128 + lane * 4;

    float4 xa = *(const float4*)(x + base + c0);
    float4 xb = *(const float4*)(x + base + c1);
    float4 ra = *(const float4*)(r + base + c0);
    float4 rb = *(const float4*)(r + base + c1);
    float4 va = make_float4(xa.x+ra.x, xa.y+ra.y, xa.z+ra.z, xa.w+ra.w);
    float4 vb = make_float4(xb.x+rb.x, xb.y+rb.y, xb.z+rb.z, xb.w+rb.w);

    float ssum = va.x+va.y+va.z+va.w + vb.x+vb.y+vb.z+vb.w;
    #pragma unroll
    for (int o = 16; o > 0; o >>= 1) ssum += __shfl_xor_sync(0xFFFFFFFFu, ssum, o);
    float mean = ssum * (1.f / E_);

    float4 da = make_float4(va.x-mean, va.y-mean, va.z-mean, va.w-mean);
    float4 db = make_float4(vb.x-mean, vb.y-mean, vb.z-mean, vb.w-mean);
    float vsum = da.x*da.x+da.y*da.y+da.z*da.z+da.w*da.w
               + db.x*db.x+db.y*db.y+db.z*db.z+db.w*db.w;
    #pragma unroll
    for (int o = 16; o > 0; o >>= 1) vsum += __shfl_xor_sync(0xFFFFFFFFu, vsum, o);
    float inv = rsqrtf(vsum * (1.f / E_) + 1e-5f);

    float4 ga = *(const float4*)(g + c0);
    float4 gb = *(const float4*)(g + c1);
    float4 ba = *(const float4*)(be + c0);
    float4 bb = *(const float4*)(be + c1);

    float4 ya = make_float4(da.x*inv*ga.x + ba.x, da.y*inv*ga.y + ba.y,
                            da.z*inv*ga.z + ba.z, da.w*inv*ga.w + ba.w);
    float4 yb = make_float4(db.x*inv*gb.x + bb.x, db.y*inv*gb.y + bb.y,
                            db.z*inv*gb.z + bb.z, db.w*inv*gb.w + bb.w);

    *(float4*)(out + base + c0) = ya;
    *(float4*)(out + base + c1) = yb;

    if (outr) {
        float4 wa = make_float4(tf32_round(ya.x), tf32_round(ya.y),
                                tf32_round(ya.z), tf32_round(ya.w));
        float4 wb = make_float4(tf32_round(yb.x), tf32_round(yb.y),
                                tf32_round(yb.z), tf32_round(yb.w));
        *(float4*)(outr + base + c0) = wa;
        *(float4*)(outr + base + c1) = wb;
    }
    if (qout) {
        float4 pa = *(const float4*)(pos + base + c0);
        float4 pb = *(const float4*)(pos + base + c1);
        float4 qa = make_float4(tf32_round(ya.x + pa.x), tf32_round(ya.y + pa.y),
                                tf32_round(ya.z + pa.z), tf32_round(ya.w + pa.w));
        float4 qb = make_float4(tf32_round(yb.x + pb.x), tf32_round(yb.y + pb.y),
                                tf32_round(yb.z + pb.z), tf32_round(yb.w + pb.w));
        *(float4*)(qout + base + c0) = qa;
        *(float4*)(qout + base + c1) = qb;
    }
}

// ---------------- host launcher ----------------
#define SMEM128 (3*(128*36 + 32*136)*4)
#define SMEM64  (3*(64*36 + 32*72)*4)

extern "C" void kernel_launch(void* const* d_in, const int* in_sizes, int n_in,
                              void* d_out, int out_size)
{
    (void)in_sizes; (void)n_in; (void)out_size;
    const float* f0 = (const float*)d_in[0];
    const float* p0 = (const float*)d_in[1];
    const float* f1 = (const float*)d_in[2];
    const float* p1 = (const float*)d_in[3];
    const float* f2 = (const float*)d_in[4];
    const float* p2 = (const float*)d_in[5];
    const float* f3 = (const float*)d_in[6];
    const float* p3 = (const float*)d_in[7];
    const float* le = (const float*)d_in[8];
    const float* W_off  = (const float*)d_in[9];
    const float* b_off  = (const float*)d_in[10];
    const float* W_attn = (const float*)d_in[11];
    const float* b_attn = (const float*)d_in[12];
    const float* W_val  = (const float*)d_in[13];
    const float* b_val  = (const float*)d_in[14];
    const float* W_out  = (const float*)d_in[15];
    const float* b_out  = (const float*)d_in[16];
    const float* ln1_g  = (const float*)d_in[17];
    const float* ln1_b  = (const float*)d_in[18];
    const float* W_ff1  = (const float*)d_in[19];
    const float* b_ff1  = (const float*)d_in[20];
    const float* W_ff2  = (const float*)d_in[21];
    const float* b_ff2  = (const float*)d_in[22];
    const float* ln2_g  = (const float*)d_in[23];
    const float* ln2_b  = (const float*)d_in[24];

    float *px, *pxr, *ppos, *pq, *pval, *psam, *ptmp, *phid, *poa;
    float *pWval, *pWqa, *pWout, *pWff1, *pWff2, *pbqa;
    cudaGetSymbolAddress((void**)&px,    g_x);
    cudaGetSymbolAddress((void**)&pxr,   g_xr);
    cudaGetSymbolAddress((void**)&ppos,  g_pos);
    cudaGetSymbolAddress((void**)&pq,    g_q);
    cudaGetSymbolAddress((void**)&pval,  g_val);
    cudaGetSymbolAddress((void**)&psam,  g_sam);
    cudaGetSymbolAddress((void**)&ptmp,  g_tmp);
    cudaGetSymbolAddress((void**)&phid,  g_hid);
    cudaGetSymbolAddress((void**)&poa,   g_oa);
    cudaGetSymbolAddress((void**)&pWval, g_Wval);
    cudaGetSymbolAddress((void**)&pWqa,  g_Wqa);
    cudaGetSymbolAddress((void**)&pWout, g_Wout);
    cudaGetSymbolAddress((void**)&pWff1, g_Wff1);
    cudaGetSymbolAddress((void**)&pWff2, g_Wff2);
    cudaGetSymbolAddress((void**)&pbqa,  g_bqa);

    cudaFuncSetAttribute(mma_gemm<128,128>, cudaFuncAttributeMaxDynamicSharedMemorySize, SMEM128);
    cudaFuncSetAttribute(mma_gemm<64,64>,   cudaFuncAttributeMaxDynamicSharedMemorySize, SMEM64);

    // weight pre-rounding / packing
    {
        int n;
        n = NLAYERS_*E_*E_;   roundcopy_kernel<<<(n+255)/256, 256>>>(pWval, W_val, n);
        n = NLAYERS_*E_*E_;   roundcopy_kernel<<<(n+255)/256, 256>>>(pWout, W_out, n);
        n = NLAYERS_*E_*DF_;  roundcopy_kernel<<<(n+255)/256, 256>>>(pWff1, W_ff1, n);
        n = NLAYERS_*DF_*E_;  roundcopy_kernel<<<(n+255)/256, 256>>>(pWff2, W_ff2, n);
        n = NLAYERS_*E_*512;  pack_qa_kernel<<<(n+255)/256, 256>>>(W_off, W_attn, b_off, b_attn);
    }

    // transposing init, one launch per level
    {
        dim3 blk(32, 32);
        init_t_kernel<<<dim3(288, 8, B_), blk>>>(f0, p0, le + 0*E_, 9216, 0);
        init_t_kernel<<<dim3( 36, 8, B_), blk>>>(f1, p1, le + 1*E_, 1152, 9216);
        init_t_kernel<<<dim3(  5, 8, B_), blk>>>(f2, p2, le + 2*E_,  144, 10368);
        init_t_kernel<<<dim3(  2, 8, B_), blk>>>(f3, p3, le + 3*E_,   36, 10512);
    }

    const int GM64  = (M_ + 63) / 64;    // 330
    const int GM128 = (M_ + 127) / 128;  // 165
    const int LNB   = M_ / 8;            // 2637

    for (int l = 0; l < NLAYERS_; l++) {
        mma_gemm<64,64><<<dim3(E_/64, GM64), 256, SMEM64>>>(pxr, pWval + (size_t)l*E_*E_,
                                           b_val + l*E_, pval, M_, E_, E_, 0);
        mma_gemm<128,128><<<dim3(512/128, GM128), 256, SMEM128>>>(pq, pWqa + (size_t)l*E_*512,
                                            pbqa + l*512, poa, M_, 512, E_, 0);

        sample_kernel<<<(M_ * NH_ * 32) / 256, 256>>>();

        mma_gemm<64,64><<<dim3(E_/64, GM64), 256, SMEM64>>>(psam, pWout + (size_t)l*E_*E_,
                                           b_out + l*E_, ptmp, M_, E_, E_, 0);
        ln8_kernel<<<LNB, 256>>>(px, ptmp, ln1_g + l*E_, ln1_b + l*E_, px, pxr,
                                 (const float*)0, (float*)0);

        mma_gemm<128,128><<<dim3(DF_/128, GM128), 256, SMEM128>>>(pxr, pWff1 + (size_t)l*E_*DF_,
                                            b_ff1 + l*DF_, phid, M_, DF_, E_, 1);
        mma_gemm<64,64><<<dim3(E_/64, GM64), 256, SMEM64>>>(phid, pWff2 + (size_t)l*DF_*E_,
                                           b_ff2 + l*E_, ptmp, M_, E_, DF_, 0);

        if (l == NLAYERS_ - 1) {
            ln8_kernel<<<LNB, 256>>>(px, ptmp, ln2_g + l*E_, ln2_b + l*E_,
                                     (float*)d_out, (float*)0, (const float*)0, (float*)0);
        } else {
            ln8_kernel<<<LNB, 256>>>(px, ptmp, ln2_g + l*E_, ln2_b + l*E_,
                                     px, pxr, ppos, pq);
        }
    }
}